// round 3
// baseline (speedup 1.0000x reference)
#include <cuda_runtime.h>
#include <cstdint>

#define NN 100000
#define EE 3200000
#define CC 32
#define LL 4
#define GG 512
#define XDIM 8
#define EDIM 4

#define QSTEP 0.0009765625f   // 2^-10
#define QINV  1024.0f
#define QMAXV (32.0f - 0.0009765625f)
#define QMINV (-32.0f)
#define BN_EPS_F 1e-5f
#define GEN_EPS_F 1e-7f
#define LOG2E_F 1.4426950408889634f
#define NEG_INF_F __int_as_float(0xff800000)

// ---------------- scratch (device globals; no allocation allowed) -------------
__device__ float d_h [NN * CC];            // node features
__device__ float d_hb[NN * CC];            // h + D_bne + eps (pre-folded for agg)
__device__ float d_h2[NN * CC];            // h + agg
__device__ uint4 d_epk[EE];                // CSR-permuted {src, k0|k1, k2|k3, 0}
__device__ int   d_deg[NN];                // zeroed at load; re-zeroed by scan_a
__device__ int   d_rowptr[NN + 1];
__device__ int   d_wp[NN];
__device__ int   d_bsum[128];
__device__ float d_pool[GG * CC];
__device__ float d_cntf[GG];

// ---------------- helpers ------------------------------------------------------
__device__ __forceinline__ float qf(float x) {
    float y = rintf(x * QINV) * QSTEP;
    return fminf(fmaxf(y, QMINV), QMAXV);
}
__device__ __forceinline__ float ex2f(float x) {
    float y;
    asm("ex2.approx.f32 %0, %1;" : "=f"(y) : "f"(x));
    return y;
}

// ---------------- node encoder: h = bn(qlin(x)) ; hb = h + D_bne + eps ----------
__global__ void k_node_enc(const float* __restrict__ x,
                           const float* __restrict__ Wn,
                           const float* __restrict__ bn_,
                           const float* __restrict__ g,
                           const float* __restrict__ b,
                           const float* __restrict__ m,
                           const float* __restrict__ v,
                           const float* __restrict__ eg,
                           const float* __restrict__ eb,
                           const float* __restrict__ em,
                           const float* __restrict__ ev) {
    __shared__ float Ws[XDIM * CC];
    __shared__ float bs[CC], As[CC], Ds[CC], Es[CC];
    int tid = threadIdx.x;
    if (tid < XDIM * CC) Ws[tid] = qf(Wn[tid]);
    if (tid < CC) {
        bs[tid] = qf(bn_[tid]);
        float rs = rsqrtf(v[tid] + BN_EPS_F);
        float a = g[tid] * rs;
        As[tid] = a;
        Ds[tid] = b[tid] - m[tid] * a;
        float ga = eg[tid] * rsqrtf(ev[tid] + BN_EPS_F);
        Es[tid] = eb[tid] - em[tid] * ga + GEN_EPS_F;   // D_bne + eps
    }
    __syncthreads();
    int node = blockIdx.x * blockDim.x + tid;
    if (node >= NN) return;
    const float4* xp = (const float4*)(x + node * XDIM);
    float4 a0 = xp[0], a1 = xp[1];
    float xq[XDIM];
    xq[0] = qf(a0.x); xq[1] = qf(a0.y); xq[2] = qf(a0.z); xq[3] = qf(a0.w);
    xq[4] = qf(a1.x); xq[5] = qf(a1.y); xq[6] = qf(a1.z); xq[7] = qf(a1.w);
    #pragma unroll
    for (int c = 0; c < CC; c++) {
        float acc = bs[c];
        #pragma unroll
        for (int k = 0; k < XDIM; k++) acc = fmaf(xq[k], Ws[k * CC + c], acc);
        float hv = fmaf(As[c], qf(acc), Ds[c]);
        d_h [node * CC + c] = hv;
        d_hb[node * CC + c] = hv + Es[c];
    }
}

// ---------------- degree histogram (+ pool zeroing piggyback) -------------------
__global__ void k_hist(const int* __restrict__ ei) {
    int e = blockIdx.x * blockDim.x + threadIdx.x;
    if (e < GG * CC) d_pool[e] = 0.0f;
    if (e < EE) atomicAdd(&d_deg[ei[EE + e]], 1);
}

// ---------------- parallel scan: block-local then per-block offset ---------------
#define SCAN_NB 98
__global__ void k_scan_a() {
    __shared__ int sh[1024];
    int tid = threadIdx.x;
    int i = blockIdx.x * 1024 + tid;
    int v = (i < NN) ? d_deg[i] : 0;
    if (i < NN) d_deg[i] = 0;                 // reset for next call
    sh[tid] = v;
    __syncthreads();
    for (int o = 1; o < 1024; o <<= 1) {
        int t = (tid >= o) ? sh[tid - o] : 0;
        __syncthreads();
        sh[tid] += t;
        __syncthreads();
    }
    if (i < NN) d_rowptr[i] = sh[tid] - v;    // block-local exclusive
    if (tid == 1023) d_bsum[blockIdx.x] = sh[1023];
}
__global__ void k_scan_b() {
    __shared__ int sh[128];
    int tid = threadIdx.x;
    if (tid < 128) sh[tid] = (tid < SCAN_NB) ? d_bsum[tid] : 0;
    __syncthreads();
    if (tid < 128) {
        #pragma unroll
        for (int o = 1; o < 128; o <<= 1) {
            int t = (tid >= o) ? sh[tid - o] : 0;
            __syncthreads();
            sh[tid] += t;
            __syncthreads();
        }
    } else {
        #pragma unroll
        for (int o = 1; o < 128; o <<= 1) { __syncthreads(); __syncthreads(); }
    }
    int off = (blockIdx.x == 0) ? 0 : sh[blockIdx.x - 1];
    int i = blockIdx.x * 1024 + tid;
    if (i < NN) {
        int r = d_rowptr[i] + off;
        d_rowptr[i] = r;
        d_wp[i] = r;
    }
    if (i == 0) d_rowptr[NN] = EE;
}

// ---------------- edge pack + CSR scatter (16B/edge) -----------------------------
__global__ void k_edge_enc(const float* __restrict__ ea,
                           const int* __restrict__ ei) {
    int e = blockIdx.x * blockDim.x + threadIdx.x;
    if (e >= EE) return;
    float4 a = ((const float4*)ea)[e];
    int k0 = max(-32768, min(32767, __float2int_rn(a.x * QINV)));
    int k1 = max(-32768, min(32767, __float2int_rn(a.y * QINV)));
    int k2 = max(-32768, min(32767, __float2int_rn(a.z * QINV)));
    int k3 = max(-32768, min(32767, __float2int_rn(a.w * QINV)));
    unsigned y = (unsigned)(k0 & 0xFFFF) | ((unsigned)k1 << 16);
    unsigned z = (unsigned)(k2 & 0xFFFF) | ((unsigned)k3 << 16);
    int src = ei[e];
    int dst = ei[EE + e];
    int pos = atomicAdd(&d_wp[dst], 1);
    __stcs(&d_epk[pos], make_uint4((unsigned)src, y, z, 0u));
}

// ---------------- GENConv softmax aggregation (recompute e, batched) -------------
#define KB 8
__global__ void __launch_bounds__(256) k_agg(const float* __restrict__ t, int l,
                      const float* __restrict__ bg, const float* __restrict__ bv,
                      const float* __restrict__ We, const float* __restrict__ be) {
    int lane = threadIdx.x & 31;
    int warp = threadIdx.x >> 5;
    int node = blockIdx.x * 8 + warp;
    if (node >= NN) return;

    // per-lane channel constants (registers)
    float w0 = qf(__ldg(We + 0 * CC + lane));
    float w1 = qf(__ldg(We + 1 * CC + lane));
    float w2 = qf(__ldg(We + 2 * CC + lane));
    float w3 = qf(__ldg(We + 3 * CC + lane));
    float bsc = qf(__ldg(be + lane)) * QINV;               // bias in tick space
    float Ap  = QSTEP * __ldg(bg + lane) * rsqrtf(__ldg(bv + lane) + BN_EPS_F);
    float tl2 = __ldg(t + l) * LOG2E_F;

    int p0 = d_rowptr[node], p1 = d_rowptr[node + 1];
    int idx4 = node * CC + lane;
    if (p0 >= p1) { d_h2[idx4] = d_h[idx4]; return; }

    float mxl = -3.402823466e38f, den = 0.0f, num = 0.0f;
    uint4 U[KB];
    float HB[KB];

    int nfull = (p1 - p0) & ~(KB - 1);
    int pe = p0 + nfull;

    for (int base = p0; base < pe; base += KB) {
        const uint4* up = d_epk + base;
        #pragma unroll
        for (int k = 0; k < KB; k++) U[k] = __ldcs(up + k);
        #pragma unroll
        for (int k = 0; k < KB; k++) HB[k] = __ldg(d_hb + (int)U[k].x * CC + lane);
        #pragma unroll
        for (int k = 0; k < KB; k++) {
            float f0 = (float)(short)(U[k].y & 0xFFFF);
            float f1 = (float)(short)(U[k].y >> 16);
            float f2 = (float)(short)(U[k].z & 0xFFFF);
            float f3 = (float)(short)(U[k].z >> 16);
            float acc = bsc;
            acc = fmaf(f0, w0, acc);
            acc = fmaf(f1, w1, acc);
            acc = fmaf(f2, w2, acc);
            acc = fmaf(f3, w3, acc);
            float tk = fminf(fmaxf(rintf(acc), -32768.0f), 32767.0f);
            float m  = fmaxf(fmaf(tk, Ap, HB[k]), GEN_EPS_F);
            float sl = m * tl2;
            float dd = sl - mxl;
            float ex = ex2f(-fabsf(dd));
            bool  upb = dd > 0.0f;
            float r  = upb ? ex : 1.0f;
            float e1 = upb ? 1.0f : ex;
            den = fmaf(den, r, e1);
            num = fmaf(num, r, e1 * m);
            mxl = fmaxf(mxl, sl);
        }
    }
    if (pe < p1) {  // masked tail batch
        #pragma unroll
        for (int k = 0; k < KB; k++) {
            int idx = min(pe + k, p1 - 1);
            U[k] = __ldcs(d_epk + idx);
        }
        #pragma unroll
        for (int k = 0; k < KB; k++) HB[k] = __ldg(d_hb + (int)U[k].x * CC + lane);
        #pragma unroll
        for (int k = 0; k < KB; k++) {
            float f0 = (float)(short)(U[k].y & 0xFFFF);
            float f1 = (float)(short)(U[k].y >> 16);
            float f2 = (float)(short)(U[k].z & 0xFFFF);
            float f3 = (float)(short)(U[k].z >> 16);
            float acc = bsc;
            acc = fmaf(f0, w0, acc);
            acc = fmaf(f1, w1, acc);
            acc = fmaf(f2, w2, acc);
            acc = fmaf(f3, w3, acc);
            float tk = fminf(fmaxf(rintf(acc), -32768.0f), 32767.0f);
            float m  = fmaxf(fmaf(tk, Ap, HB[k]), GEN_EPS_F);
            float sl = (pe + k < p1) ? m * tl2 : NEG_INF_F;
            float dd = sl - mxl;
            float ex = ex2f(-fabsf(dd));
            bool  upb = dd > 0.0f;
            float r  = upb ? ex : 1.0f;
            float e1 = upb ? 1.0f : ex;
            den = fmaf(den, r, e1);
            num = fmaf(num, r, e1 * m);
            mxl = fmaxf(mxl, sl);
        }
    }
    float agg = num / fmaxf(den, 1e-16f);
    d_h2[idx4] = d_h[idx4] + agg;
}

// ---------------- per-layer quantized MLP + residual (+ hb emit) -----------------
__global__ void __launch_bounds__(128) k_mlp(int l,
        const float* __restrict__ W1, const float* __restrict__ b1,
        const float* __restrict__ g1, const float* __restrict__ bb1,
        const float* __restrict__ m1, const float* __restrict__ v1,
        const float* __restrict__ W2, const float* __restrict__ b2,
        const float* __restrict__ eg, const float* __restrict__ eb,
        const float* __restrict__ em, const float* __restrict__ ev) {
    __shared__ float w1s[CC * 2 * CC];
    __shared__ float w2s[2 * CC * CC];
    __shared__ float b1s[2 * CC], a1s[2 * CC], d1s[2 * CC], b2s[CC], Es[CC];
    int tid = threadIdx.x;
    const float* W1l = W1 + l * CC * 2 * CC;
    const float* W2l = W2 + l * 2 * CC * CC;
    for (int i = tid; i < CC * 2 * CC; i += 128) {
        w1s[i] = qf(W1l[i]);
        w2s[i] = qf(W2l[i]);
    }
    if (tid < 2 * CC) {
        b1s[tid] = qf(b1[l * 2 * CC + tid]);
        float rsv = rsqrtf(v1[l * 2 * CC + tid] + BN_EPS_F);
        float a = g1[l * 2 * CC + tid] * rsv;
        a1s[tid] = a;
        d1s[tid] = bb1[l * 2 * CC + tid] - m1[l * 2 * CC + tid] * a;
    }
    if (tid < CC) {
        b2s[tid] = qf(b2[l * CC + tid]);
        float ga = eg[tid] * rsqrtf(ev[tid] + BN_EPS_F);
        Es[tid] = eb[tid] - em[tid] * ga + GEN_EPS_F;
    }
    __syncthreads();

    int node = blockIdx.x * 128 + tid;
    if (node >= NN) return;

    float xq[CC];
    const float4* hp = (const float4*)(d_h2 + node * CC);
    #pragma unroll
    for (int i = 0; i < 8; i++) {
        float4 t4 = hp[i];
        xq[4 * i + 0] = qf(t4.x); xq[4 * i + 1] = qf(t4.y);
        xq[4 * i + 2] = qf(t4.z); xq[4 * i + 3] = qf(t4.w);
    }
    float acc2[CC];
    #pragma unroll
    for (int c = 0; c < CC; c++) acc2[c] = b2s[c];

    for (int j = 0; j < 2 * CC; j++) {
        float a = b1s[j];
        #pragma unroll
        for (int k = 0; k < CC; k++) a = fmaf(xq[k], w1s[k * 2 * CC + j], a);
        float z1 = qf(a);
        float zr = qf(fmaxf(fmaf(a1s[j], z1, d1s[j]), 0.0f));
        #pragma unroll
        for (int c = 0; c < CC; c++) acc2[c] = fmaf(zr, w2s[j * CC + c], acc2[c]);
    }
    bool emit_hb = (l < LL - 1);
    const float4* ip = (const float4*)(d_h + node * CC);
    float4* op = (float4*)(d_h + node * CC);
    float4* bp = (float4*)(d_hb + node * CC);
    #pragma unroll
    for (int c = 0; c < CC; c += 4) {
        float4 id4 = ip[c >> 2];
        float4 o;
        o.x = qf(acc2[c + 0]) + id4.x;
        o.y = qf(acc2[c + 1]) + id4.y;
        o.z = qf(acc2[c + 2]) + id4.z;
        o.w = qf(acc2[c + 3]) + id4.w;
        op[c >> 2] = o;
        if (emit_hb) {
            float4 hbv;
            hbv.x = o.x + Es[c + 0];
            hbv.y = o.y + Es[c + 1];
            hbv.z = o.z + Es[c + 2];
            hbv.w = o.w + Es[c + 3];
            bp[c >> 2] = hbv;
        }
    }
}

// ---------------- global mean pool ----------------------------------------------
__global__ void k_pool(const int* __restrict__ batch) {
    int lane = threadIdx.x & 31;
    int w = (blockIdx.x * blockDim.x + threadIdx.x) >> 5;
    const int CHUNK = 128;
    int i0 = w * CHUNK;
    if (i0 >= NN) return;
    int i1 = min(i0 + CHUNK, NN);
    int cur = batch[i0];
    float acc = 0.0f;
    for (int i = i0; i < i1; i++) {
        int g = batch[i];
        float val = d_h[i * CC + lane];
        if (g != cur) {
            atomicAdd(&d_pool[cur * CC + lane], acc);
            acc = 0.0f;
            cur = g;
        }
        acc += val;
    }
    atomicAdd(&d_pool[cur * CC + lane], acc);
}

__global__ void k_cnt(const int* __restrict__ batch) {
    int g = blockIdx.x * blockDim.x + threadIdx.x;
    if (g >= GG) return;
    int lo0 = 0, hi0 = NN;
    while (lo0 < hi0) { int mid = (lo0 + hi0) >> 1; if (batch[mid] < g) lo0 = mid + 1; else hi0 = mid; }
    int lo1 = lo0, hi1 = NN;
    while (lo1 < hi1) { int mid = (lo1 + hi1) >> 1; if (batch[mid] < g + 1) lo1 = mid + 1; else hi1 = mid; }
    d_cntf[g] = (float)(lo1 - lo0);
}

__global__ void k_final(const float* __restrict__ Wo, const float* __restrict__ bo,
                        float* __restrict__ out) {
    __shared__ float wq[CC];
    int tid = threadIdx.x;
    if (tid < CC) wq[tid] = qf(Wo[tid]);
    __syncthreads();
    int g = blockIdx.x * blockDim.x + tid;
    if (g >= GG) return;
    float cnt = fmaxf(d_cntf[g], 1.0f);
    float acc = qf(bo[0]);
    #pragma unroll
    for (int c = 0; c < CC; c++) {
        float pm = d_pool[g * CC + c] / cnt;
        acc = fmaf(qf(pm), wq[c], acc);
    }
    float o = qf(acc);
    float s = 1.0f / (1.0f + expf(-o));
    out[g] = qf(s);
}

// ---------------- launch ---------------------------------------------------------
extern "C" void kernel_launch(void* const* d_in, const int* in_sizes, int n_in,
                              void* d_out, int out_size) {
    const float* x    = (const float*)d_in[0];
    const float* ea   = (const float*)d_in[1];
    const float* Wn   = (const float*)d_in[2];
    const float* bn_  = (const float*)d_in[3];
    const float* We   = (const float*)d_in[4];
    const float* be   = (const float*)d_in[5];
    const float* bnng = (const float*)d_in[6];
    const float* bnnb = (const float*)d_in[7];
    const float* bnnm = (const float*)d_in[8];
    const float* bnnv = (const float*)d_in[9];
    const float* bneg = (const float*)d_in[10];
    const float* bneb = (const float*)d_in[11];
    const float* bnem = (const float*)d_in[12];
    const float* bnev = (const float*)d_in[13];
    const float* t    = (const float*)d_in[14];
    const float* W1   = (const float*)d_in[15];
    const float* b1   = (const float*)d_in[16];
    const float* g1   = (const float*)d_in[17];
    const float* bb1  = (const float*)d_in[18];
    const float* m1   = (const float*)d_in[19];
    const float* v1   = (const float*)d_in[20];
    const float* W2   = (const float*)d_in[21];
    const float* b2   = (const float*)d_in[22];
    const float* Wo   = (const float*)d_in[23];
    const float* bo   = (const float*)d_in[24];
    const int*   ei   = (const int*)d_in[25];
    const int*   batch= (const int*)d_in[26];
    float* out = (float*)d_out;

    k_node_enc<<<(NN + 255) / 256, 256>>>(x, Wn, bn_, bnng, bnnb, bnnm, bnnv,
                                          bneg, bneb, bnem, bnev);
    k_hist<<<(EE + 255) / 256, 256>>>(ei);
    k_scan_a<<<SCAN_NB, 1024>>>();
    k_scan_b<<<SCAN_NB, 1024>>>();
    k_edge_enc<<<(EE + 255) / 256, 256>>>(ea, ei);

    for (int l = 0; l < LL; l++) {
        k_agg<<<(NN + 7) / 8, 256>>>(t, l, bneg, bnev, We, be);
        k_mlp<<<(NN + 127) / 128, 128>>>(l, W1, b1, g1, bb1, m1, v1, W2, b2,
                                         bneg, bneb, bnem, bnev);
    }

    k_pool<<<98, 256>>>(batch);
    k_cnt<<<(GG + 255) / 256, 256>>>(batch);
    k_final<<<(GG + 255) / 256, 256>>>(Wo, bo, out);
}

// round 4
// speedup vs baseline: 1.1645x; 1.1645x over previous
#include <cuda_runtime.h>
#include <cstdint>

#define NN 100000
#define EE 3200000
#define CC 32
#define LL 4
#define GG 512
#define XDIM 8
#define EDIM 4

#define QSTEP 0.0009765625f   // 2^-10
#define QINV  1024.0f
#define QMAXV (32.0f - 0.0009765625f)
#define QMINV (-32.0f)
#define BN_EPS_F 1e-5f
#define GEN_EPS_F 1e-7f
#define LOG2E_F 1.4426950408889634f

// ---------------- scratch (device globals; no allocation allowed) -------------
__device__ float d_h [NN * CC];            // node features
__device__ float d_hb[NN * CC];            // h + D_bne + eps (pre-folded for agg)
__device__ float d_h2[NN * CC];            // h + agg
__device__ short d_eq[(size_t)EE * CC];    // CSR-permuted quantized edge features
__device__ int   d_srcp[EE];               // CSR-permuted src ids
__device__ int   d_deg[NN];                // zeroed at load; re-zeroed by edge_enc
__device__ int   d_rowptr[NN + 1];
__device__ int   d_wp[NN];
__device__ float d_pool[GG * CC];
__device__ float d_cntf[GG];

// ---------------- helpers ------------------------------------------------------
__device__ __forceinline__ float qf(float x) {
    float y = rintf(x * QINV) * QSTEP;
    return fminf(fmaxf(y, QMINV), QMAXV);
}
__device__ __forceinline__ float ex2f(float x) {
    float y;
    asm("ex2.approx.f32 %0, %1;" : "=f"(y) : "f"(x));
    return y;
}

// ---------------- fused: node encoder + degree hist + pool zero -----------------
__global__ void k_pre(const float* __restrict__ x,
                      const float* __restrict__ Wn,
                      const float* __restrict__ bn_,
                      const float* __restrict__ g,
                      const float* __restrict__ b,
                      const float* __restrict__ m,
                      const float* __restrict__ v,
                      const float* __restrict__ eg,
                      const float* __restrict__ eb,
                      const float* __restrict__ em,
                      const float* __restrict__ ev,
                      const int* __restrict__ ei) {
    __shared__ float Ws[XDIM * CC];
    __shared__ float bs[CC], As[CC], Ds[CC], Es[CC];
    int tid = threadIdx.x;
    int gi = blockIdx.x * blockDim.x + tid;

    if (tid < XDIM * CC) Ws[tid] = qf(Wn[tid]);
    if (tid < CC) {
        bs[tid] = qf(bn_[tid]);
        float rs = rsqrtf(v[tid] + BN_EPS_F);
        float a = g[tid] * rs;
        As[tid] = a;
        Ds[tid] = b[tid] - m[tid] * a;
        float ga = eg[tid] * rsqrtf(ev[tid] + BN_EPS_F);
        Es[tid] = eb[tid] - em[tid] * ga + GEN_EPS_F;   // D_bne + eps
    }

    if (gi < GG * CC) d_pool[gi] = 0.0f;
    if (gi < EE) atomicAdd(&d_deg[ei[EE + gi]], 1);

    __syncthreads();
    if (gi >= NN) return;

    const float4* xp = (const float4*)(x + gi * XDIM);
    float4 a0 = xp[0], a1 = xp[1];
    float xq[XDIM];
    xq[0] = qf(a0.x); xq[1] = qf(a0.y); xq[2] = qf(a0.z); xq[3] = qf(a0.w);
    xq[4] = qf(a1.x); xq[5] = qf(a1.y); xq[6] = qf(a1.z); xq[7] = qf(a1.w);
    #pragma unroll
    for (int c = 0; c < CC; c++) {
        float acc = bs[c];
        #pragma unroll
        for (int k = 0; k < XDIM; k++) acc = fmaf(xq[k], Ws[k * CC + c], acc);
        float hv = fmaf(As[c], qf(acc), Ds[c]);
        d_h [gi * CC + c] = hv;
        d_hb[gi * CC + c] = hv + Es[c];
    }
}

// ---------------- single-launch scan (redundant per-block prefix) ---------------
#define SCAN_NB 98
__global__ void k_scan() {
    __shared__ int sh[1024];
    __shared__ int red[32];
    int tid = threadIdx.x;
    int lane = tid & 31, wid = tid >> 5;
    int bid = blockIdx.x;

    // 1) offset = sum of deg[0 .. bid*1024)
    int lim = bid * 1024;
    int acc = 0;
    for (int i = tid; i < lim; i += 1024) acc += d_deg[i];
    #pragma unroll
    for (int o = 16; o > 0; o >>= 1) acc += __shfl_down_sync(0xFFFFFFFF, acc, o);
    if (lane == 0) red[wid] = acc;
    __syncthreads();
    int off;
    {
        int a2 = (lane < 32) ? red[lane] : 0;
        #pragma unroll
        for (int o = 16; o > 0; o >>= 1) a2 += __shfl_down_sync(0xFFFFFFFF, a2, o);
        off = __shfl_sync(0xFFFFFFFF, a2, 0);
    }

    // 2) scan own chunk
    int i = bid * 1024 + tid;
    int v = (i < NN) ? d_deg[i] : 0;
    sh[tid] = v;
    __syncthreads();
    for (int o = 1; o < 1024; o <<= 1) {
        int t = (tid >= o) ? sh[tid - o] : 0;
        __syncthreads();
        sh[tid] += t;
        __syncthreads();
    }
    if (i < NN) {
        int r = sh[tid] - v + off;
        d_rowptr[i] = r;
        d_wp[i] = r;
    }
    if (bid == 0 && tid == 0) d_rowptr[NN] = EE;
}

// ---------------- edge encoder + CSR scatter (+ deg reset) ----------------------
__global__ void k_edge_enc(const float* __restrict__ ea,
                           const float* __restrict__ We,
                           const float* __restrict__ be,
                           const int* __restrict__ ei) {
    __shared__ float Ws[EDIM * CC];
    __shared__ float bs[CC];
    int tid = threadIdx.x;
    if (tid < EDIM * CC) Ws[tid] = qf(We[tid]);
    if (tid < CC) bs[tid] = qf(be[tid]);
    __syncthreads();
    int e = blockIdx.x * blockDim.x + tid;
    if (e < NN) d_deg[e] = 0;                 // reset for next call
    if (e >= EE) return;
    float4 a = ((const float4*)ea)[e];
    float x0 = qf(a.x), x1 = qf(a.y), x2 = qf(a.z), x3 = qf(a.w);
    unsigned int us[16];
    #pragma unroll
    for (int c = 0; c < CC; c += 2) {
        float acc0 = bs[c], acc1 = bs[c + 1];
        acc0 = fmaf(x0, Ws[0 * CC + c], acc0);
        acc0 = fmaf(x1, Ws[1 * CC + c], acc0);
        acc0 = fmaf(x2, Ws[2 * CC + c], acc0);
        acc0 = fmaf(x3, Ws[3 * CC + c], acc0);
        acc1 = fmaf(x0, Ws[0 * CC + c + 1], acc1);
        acc1 = fmaf(x1, Ws[1 * CC + c + 1], acc1);
        acc1 = fmaf(x2, Ws[2 * CC + c + 1], acc1);
        acc1 = fmaf(x3, Ws[3 * CC + c + 1], acc1);
        int k0 = __float2int_rn(acc0 * QINV);
        int k1 = __float2int_rn(acc1 * QINV);
        k0 = max(-32768, min(32767, k0));
        k1 = max(-32768, min(32767, k1));
        us[c >> 1] = (unsigned)(k0 & 0xFFFF) | ((unsigned)k1 << 16);
    }
    int src = ei[e];
    int dst = ei[EE + e];
    int pos = atomicAdd(&d_wp[dst], 1);
    d_srcp[pos] = src;
    uint4* o = (uint4*)(d_eq + (size_t)pos * CC);
    __stcs(o + 0, make_uint4(us[0],  us[1],  us[2],  us[3]));
    __stcs(o + 1, make_uint4(us[4],  us[5],  us[6],  us[7]));
    __stcs(o + 2, make_uint4(us[8],  us[9],  us[10], us[11]));
    __stcs(o + 3, make_uint4(us[12], us[13], us[14], us[15]));
}

// ---------------- GENConv softmax aggregation (simple streaming loop) -----------
__global__ void __launch_bounds__(256) k_agg(const float* __restrict__ t, int l,
                      const float* __restrict__ bg, const float* __restrict__ bv) {
    int lane = threadIdx.x & 31;
    int warp = threadIdx.x >> 5;
    int node = blockIdx.x * 8 + warp;
    if (node >= NN) return;

    float A   = QSTEP * __ldg(bg + lane) * rsqrtf(__ldg(bv + lane) + BN_EPS_F);
    float tl2 = __ldg(t + l) * LOG2E_F;

    int p0 = d_rowptr[node], p1 = d_rowptr[node + 1];
    float mxl = -3.402823466e38f, den = 0.0f, num = 0.0f;
    const short* eqp = d_eq + (size_t)p0 * CC + lane;

    #pragma unroll 4
    for (int p = p0; p < p1; ++p) {
        int   src = __ldcs(d_srcp + p);
        short kv  = __ldcs(eqp);
        eqp += CC;
        float hbv = __ldg(d_hb + src * CC + lane);
        float m   = fmaxf(fmaf((float)kv, A, hbv), GEN_EPS_F);
        float sl  = m * tl2;
        float dd  = sl - mxl;
        float ex  = ex2f(-fabsf(dd));
        bool  up  = dd > 0.0f;
        float r   = up ? ex : 1.0f;
        float e1  = up ? 1.0f : ex;
        den = fmaf(den, r, e1);
        num = fmaf(num, r, e1 * m);
        mxl = fmaxf(mxl, sl);
    }
    float agg = num / fmaxf(den, 1e-16f);
    int idx = node * CC + lane;
    d_h2[idx] = d_h[idx] + agg;
}

// ---------------- per-layer quantized MLP + residual (+ hb emit) -----------------
__global__ void __launch_bounds__(128) k_mlp(int l,
        const float* __restrict__ W1, const float* __restrict__ b1,
        const float* __restrict__ g1, const float* __restrict__ bb1,
        const float* __restrict__ m1, const float* __restrict__ v1,
        const float* __restrict__ W2, const float* __restrict__ b2,
        const float* __restrict__ eg, const float* __restrict__ eb,
        const float* __restrict__ em, const float* __restrict__ ev) {
    __shared__ float w1s[CC * 2 * CC];
    __shared__ float w2s[2 * CC * CC];
    __shared__ float b1s[2 * CC], a1s[2 * CC], d1s[2 * CC], b2s[CC], Es[CC];
    int tid = threadIdx.x;
    const float* W1l = W1 + l * CC * 2 * CC;
    const float* W2l = W2 + l * 2 * CC * CC;
    for (int i = tid; i < CC * 2 * CC; i += 128) {
        w1s[i] = qf(W1l[i]);
        w2s[i] = qf(W2l[i]);
    }
    if (tid < 2 * CC) {
        b1s[tid] = qf(b1[l * 2 * CC + tid]);
        float rsv = rsqrtf(v1[l * 2 * CC + tid] + BN_EPS_F);
        float a = g1[l * 2 * CC + tid] * rsv;
        a1s[tid] = a;
        d1s[tid] = bb1[l * 2 * CC + tid] - m1[l * 2 * CC + tid] * a;
    }
    if (tid < CC) {
        b2s[tid] = qf(b2[l * CC + tid]);
        float ga = eg[tid] * rsqrtf(ev[tid] + BN_EPS_F);
        Es[tid] = eb[tid] - em[tid] * ga + GEN_EPS_F;
    }
    __syncthreads();

    int node = blockIdx.x * 128 + tid;
    if (node >= NN) return;

    float xq[CC];
    const float4* hp = (const float4*)(d_h2 + node * CC);
    #pragma unroll
    for (int i = 0; i < 8; i++) {
        float4 t4 = hp[i];
        xq[4 * i + 0] = qf(t4.x); xq[4 * i + 1] = qf(t4.y);
        xq[4 * i + 2] = qf(t4.z); xq[4 * i + 3] = qf(t4.w);
    }
    float acc2[CC];
    #pragma unroll
    for (int c = 0; c < CC; c++) acc2[c] = b2s[c];

    for (int j = 0; j < 2 * CC; j++) {
        float a = b1s[j];
        #pragma unroll
        for (int k = 0; k < CC; k++) a = fmaf(xq[k], w1s[k * 2 * CC + j], a);
        float z1 = qf(a);
        float zr = qf(fmaxf(fmaf(a1s[j], z1, d1s[j]), 0.0f));
        #pragma unroll
        for (int c = 0; c < CC; c++) acc2[c] = fmaf(zr, w2s[j * CC + c], acc2[c]);
    }
    bool emit_hb = (l < LL - 1);
    const float4* ip = (const float4*)(d_h + node * CC);
    float4* op = (float4*)(d_h + node * CC);
    float4* bp = (float4*)(d_hb + node * CC);
    #pragma unroll
    for (int c = 0; c < CC; c += 4) {
        float4 id4 = ip[c >> 2];
        float4 o;
        o.x = qf(acc2[c + 0]) + id4.x;
        o.y = qf(acc2[c + 1]) + id4.y;
        o.z = qf(acc2[c + 2]) + id4.z;
        o.w = qf(acc2[c + 3]) + id4.w;
        op[c >> 2] = o;
        if (emit_hb) {
            float4 hbv;
            hbv.x = o.x + Es[c + 0];
            hbv.y = o.y + Es[c + 1];
            hbv.z = o.z + Es[c + 2];
            hbv.w = o.w + Es[c + 3];
            bp[c >> 2] = hbv;
        }
    }
}

// ---------------- global mean pool ----------------------------------------------
__global__ void k_pool(const int* __restrict__ batch) {
    int lane = threadIdx.x & 31;
    int w = (blockIdx.x * blockDim.x + threadIdx.x) >> 5;
    const int CHUNK = 128;
    int i0 = w * CHUNK;
    if (i0 >= NN) return;
    int i1 = min(i0 + CHUNK, NN);
    int cur = batch[i0];
    float acc = 0.0f;
    for (int i = i0; i < i1; i++) {
        int g = batch[i];
        float val = d_h[i * CC + lane];
        if (g != cur) {
            atomicAdd(&d_pool[cur * CC + lane], acc);
            acc = 0.0f;
            cur = g;
        }
        acc += val;
    }
    atomicAdd(&d_pool[cur * CC + lane], acc);
}

__global__ void k_cnt(const int* __restrict__ batch) {
    int g = blockIdx.x * blockDim.x + threadIdx.x;
    if (g >= GG) return;
    int lo0 = 0, hi0 = NN;
    while (lo0 < hi0) { int mid = (lo0 + hi0) >> 1; if (batch[mid] < g) lo0 = mid + 1; else hi0 = mid; }
    int lo1 = lo0, hi1 = NN;
    while (lo1 < hi1) { int mid = (lo1 + hi1) >> 1; if (batch[mid] < g + 1) lo1 = mid + 1; else hi1 = mid; }
    d_cntf[g] = (float)(lo1 - lo0);
}

__global__ void k_final(const float* __restrict__ Wo, const float* __restrict__ bo,
                        float* __restrict__ out) {
    __shared__ float wq[CC];
    int tid = threadIdx.x;
    if (tid < CC) wq[tid] = qf(Wo[tid]);
    __syncthreads();
    int g = blockIdx.x * blockDim.x + tid;
    if (g >= GG) return;
    float cnt = fmaxf(d_cntf[g], 1.0f);
    float acc = qf(bo[0]);
    #pragma unroll
    for (int c = 0; c < CC; c++) {
        float pm = d_pool[g * CC + c] / cnt;
        acc = fmaf(qf(pm), wq[c], acc);
    }
    float o = qf(acc);
    float s = 1.0f / (1.0f + expf(-o));
    out[g] = qf(s);
}

// ---------------- launch ---------------------------------------------------------
extern "C" void kernel_launch(void* const* d_in, const int* in_sizes, int n_in,
                              void* d_out, int out_size) {
    const float* x    = (const float*)d_in[0];
    const float* ea   = (const float*)d_in[1];
    const float* Wn   = (const float*)d_in[2];
    const float* bn_  = (const float*)d_in[3];
    const float* We   = (const float*)d_in[4];
    const float* be   = (const float*)d_in[5];
    const float* bnng = (const float*)d_in[6];
    const float* bnnb = (const float*)d_in[7];
    const float* bnnm = (const float*)d_in[8];
    const float* bnnv = (const float*)d_in[9];
    const float* bneg = (const float*)d_in[10];
    const float* bneb = (const float*)d_in[11];
    const float* bnem = (const float*)d_in[12];
    const float* bnev = (const float*)d_in[13];
    const float* t    = (const float*)d_in[14];
    const float* W1   = (const float*)d_in[15];
    const float* b1   = (const float*)d_in[16];
    const float* g1   = (const float*)d_in[17];
    const float* bb1  = (const float*)d_in[18];
    const float* m1   = (const float*)d_in[19];
    const float* v1   = (const float*)d_in[20];
    const float* W2   = (const float*)d_in[21];
    const float* b2   = (const float*)d_in[22];
    const float* Wo   = (const float*)d_in[23];
    const float* bo   = (const float*)d_in[24];
    const int*   ei   = (const int*)d_in[25];
    const int*   batch= (const int*)d_in[26];
    float* out = (float*)d_out;

    k_pre<<<(EE + 255) / 256, 256>>>(x, Wn, bn_, bnng, bnnb, bnnm, bnnv,
                                     bneg, bneb, bnem, bnev, ei);
    k_scan<<<SCAN_NB, 1024>>>();
    k_edge_enc<<<(EE + 255) / 256, 256>>>(ea, We, be, ei);

    for (int l = 0; l < LL; l++) {
        k_agg<<<(NN + 7) / 8, 256>>>(t, l, bneg, bnev);
        k_mlp<<<(NN + 127) / 128, 128>>>(l, W1, b1, g1, bb1, m1, v1, W2, b2,
                                         bneg, bneb, bnem, bnev);
    }

    k_pool<<<98, 256>>>(batch);
    k_cnt<<<(GG + 255) / 256, 256>>>(batch);
    k_final<<<(GG + 255) / 256, 256>>>(Wo, bo, out);
}

// round 5
// speedup vs baseline: 1.1864x; 1.0188x over previous
#include <cuda_runtime.h>
#include <cstdint>

#define NN 100000
#define EE 3200000
#define CC 32
#define LL 4
#define GG 512
#define XDIM 8
#define EDIM 4

#define QSTEP 0.0009765625f   // 2^-10
#define QINV  1024.0f
#define QMAXV (32.0f - 0.0009765625f)
#define QMINV (-32.0f)
#define BN_EPS_F 1e-5f
#define GEN_EPS_F 1e-7f
#define LOG2E_F 1.4426950408889634f

// ---------------- scratch (device globals; no allocation allowed) -------------
__device__ float d_h [NN * CC];            // node features
__device__ float d_hb[NN * CC];            // (h + D_bne + eps) * t[l]*log2e  (pre-scaled)
__device__ float d_h2[NN * CC];            // h + agg
__device__ short d_eq[(size_t)EE * CC];    // CSR-permuted quantized edge features
__device__ int   d_srcp[EE];               // CSR-permuted src ids
__device__ uint4 d_epk[EE];                // CSR-permuted packs {src, k01, k23, 0}
__device__ int   d_deg[NN];                // zeroed at load; re-zeroed by k_epack
__device__ int   d_rowptr[NN + 1];
__device__ int   d_wp[NN];
__device__ float d_pool[GG * CC];
__device__ float d_cntf[GG];

// ---------------- helpers ------------------------------------------------------
__device__ __forceinline__ float qf(float x) {
    float y = rintf(x * QINV) * QSTEP;
    return fminf(fmaxf(y, QMINV), QMAXV);
}
__device__ __forceinline__ float ex2f(float x) {
    float y;
    asm("ex2.approx.f32 %0, %1;" : "=f"(y) : "f"(x));
    return y;
}

// ---------------- fused: node encoder + degree hist + pool zero -----------------
__global__ void k_pre(const float* __restrict__ x,
                      const float* __restrict__ Wn,
                      const float* __restrict__ bn_,
                      const float* __restrict__ g,
                      const float* __restrict__ b,
                      const float* __restrict__ m,
                      const float* __restrict__ v,
                      const float* __restrict__ eg,
                      const float* __restrict__ eb,
                      const float* __restrict__ em,
                      const float* __restrict__ ev,
                      const float* __restrict__ t,
                      const int* __restrict__ ei) {
    __shared__ float Ws[XDIM * CC];
    __shared__ float bs[CC], As[CC], Ds[CC], Es[CC];
    int tid = threadIdx.x;
    int gi = blockIdx.x * blockDim.x + tid;

    if (tid < XDIM * CC) Ws[tid] = qf(Wn[tid]);
    if (tid < CC) {
        bs[tid] = qf(bn_[tid]);
        float rs = rsqrtf(v[tid] + BN_EPS_F);
        float a = g[tid] * rs;
        As[tid] = a;
        Ds[tid] = b[tid] - m[tid] * a;
        float ga = eg[tid] * rsqrtf(ev[tid] + BN_EPS_F);
        Es[tid] = eb[tid] - em[tid] * ga + GEN_EPS_F;   // D_bne + eps
    }

    if (gi < GG * CC) d_pool[gi] = 0.0f;
    if (gi < EE) atomicAdd(&d_deg[ei[EE + gi]], 1);

    __syncthreads();
    if (gi >= NN) return;

    float tl2 = __ldg(t) * LOG2E_F;           // t[0]
    const float4* xp = (const float4*)(x + gi * XDIM);
    float4 a0 = xp[0], a1 = xp[1];
    float xq[XDIM];
    xq[0] = qf(a0.x); xq[1] = qf(a0.y); xq[2] = qf(a0.z); xq[3] = qf(a0.w);
    xq[4] = qf(a1.x); xq[5] = qf(a1.y); xq[6] = qf(a1.z); xq[7] = qf(a1.w);
    #pragma unroll
    for (int c = 0; c < CC; c++) {
        float acc = bs[c];
        #pragma unroll
        for (int k = 0; k < XDIM; k++) acc = fmaf(xq[k], Ws[k * CC + c], acc);
        float hv = fmaf(As[c], qf(acc), Ds[c]);
        d_h [gi * CC + c] = hv;
        d_hb[gi * CC + c] = (hv + Es[c]) * tl2;
    }
}

// ---------------- single-launch scan (redundant per-block prefix) ---------------
#define SCAN_NB 98
__global__ void k_scan() {
    __shared__ int sh[1024];
    __shared__ int red[32];
    int tid = threadIdx.x;
    int lane = tid & 31, wid = tid >> 5;
    int bid = blockIdx.x;

    int lim = bid * 1024;
    int acc = 0;
    for (int i = tid; i < lim; i += 1024) acc += d_deg[i];
    #pragma unroll
    for (int o = 16; o > 0; o >>= 1) acc += __shfl_down_sync(0xFFFFFFFF, acc, o);
    if (lane == 0) red[wid] = acc;
    __syncthreads();
    int off;
    {
        int a2 = red[lane];
        #pragma unroll
        for (int o = 16; o > 0; o >>= 1) a2 += __shfl_down_sync(0xFFFFFFFF, a2, o);
        off = __shfl_sync(0xFFFFFFFF, a2, 0);
    }

    int i = bid * 1024 + tid;
    int v = (i < NN) ? d_deg[i] : 0;
    sh[tid] = v;
    __syncthreads();
    for (int o = 1; o < 1024; o <<= 1) {
        int t = (tid >= o) ? sh[tid - o] : 0;
        __syncthreads();
        sh[tid] += t;
        __syncthreads();
    }
    if (i < NN) {
        int r = sh[tid] - v + off;
        d_rowptr[i] = r;
        d_wp[i] = r;
    }
    if (bid == 0 && tid == 0) d_rowptr[NN] = EE;
}

// ---------------- phase 1: pack + CSR scatter (16B/edge) + deg reset ------------
__global__ void k_epack(const float* __restrict__ ea,
                        const int* __restrict__ ei) {
    int e = blockIdx.x * blockDim.x + threadIdx.x;
    if (e < NN) d_deg[e] = 0;                 // reset for next call
    if (e >= EE) return;
    float4 a = ((const float4*)ea)[e];
    int k0 = max(-32768, min(32767, __float2int_rn(a.x * QINV)));
    int k1 = max(-32768, min(32767, __float2int_rn(a.y * QINV)));
    int k2 = max(-32768, min(32767, __float2int_rn(a.z * QINV)));
    int k3 = max(-32768, min(32767, __float2int_rn(a.w * QINV)));
    unsigned y = (unsigned)(k0 & 0xFFFF) | ((unsigned)k1 << 16);
    unsigned z = (unsigned)(k2 & 0xFFFF) | ((unsigned)k3 << 16);
    int src = ei[e];
    int dst = ei[EE + e];
    int pos = atomicAdd(&d_wp[dst], 1);
    __stcs(&d_epk[pos], make_uint4((unsigned)src, y, z, 0u));
}

// ---------------- phase 2: sequential expand to eq rows + srcp ------------------
__global__ void k_eexpand(const float* __restrict__ We,
                          const float* __restrict__ be) {
    __shared__ float Ws[EDIM * CC];   // qf(W) * QSTEP (tick-space, exact)
    __shared__ float bs[CC];
    int tid = threadIdx.x;
    if (tid < EDIM * CC) Ws[tid] = qf(We[tid]) * QSTEP;
    if (tid < CC) bs[tid] = qf(be[tid]);
    __syncthreads();
    int e = blockIdx.x * blockDim.x + tid;
    if (e >= EE) return;
    uint4 u = __ldcs(&d_epk[e]);
    float f0 = (float)(short)(u.y & 0xFFFF);
    float f1 = (float)(short)(u.y >> 16);
    float f2 = (float)(short)(u.z & 0xFFFF);
    float f3 = (float)(short)(u.z >> 16);
    d_srcp[e] = (int)u.x;
    unsigned int us[16];
    #pragma unroll
    for (int c = 0; c < CC; c += 2) {
        float acc0 = bs[c], acc1 = bs[c + 1];
        acc0 = fmaf(f0, Ws[0 * CC + c], acc0);
        acc0 = fmaf(f1, Ws[1 * CC + c], acc0);
        acc0 = fmaf(f2, Ws[2 * CC + c], acc0);
        acc0 = fmaf(f3, Ws[3 * CC + c], acc0);
        acc1 = fmaf(f0, Ws[0 * CC + c + 1], acc1);
        acc1 = fmaf(f1, Ws[1 * CC + c + 1], acc1);
        acc1 = fmaf(f2, Ws[2 * CC + c + 1], acc1);
        acc1 = fmaf(f3, Ws[3 * CC + c + 1], acc1);
        int k0 = __float2int_rn(acc0 * QINV);
        int k1 = __float2int_rn(acc1 * QINV);
        k0 = max(-32768, min(32767, k0));
        k1 = max(-32768, min(32767, k1));
        us[c >> 1] = (unsigned)(k0 & 0xFFFF) | ((unsigned)k1 << 16);
    }
    uint4* o = (uint4*)(d_eq + (size_t)e * CC);
    o[0] = make_uint4(us[0],  us[1],  us[2],  us[3]);
    o[1] = make_uint4(us[4],  us[5],  us[6],  us[7]);
    o[2] = make_uint4(us[8],  us[9],  us[10], us[11]);
    o[3] = make_uint4(us[12], us[13], us[14], us[15]);
}

// ---------------- GENConv softmax aggregation (2-exp online form) ---------------
__global__ void __launch_bounds__(256) k_agg(const float* __restrict__ t, int l,
                      const float* __restrict__ bg, const float* __restrict__ bv) {
    int lane = threadIdx.x & 31;
    int warp = threadIdx.x >> 5;
    int node = blockIdx.x * 8 + warp;
    if (node >= NN) return;

    float tl2  = __ldg(t + l) * LOG2E_F;
    float A2   = QSTEP * __ldg(bg + lane) * rsqrtf(__ldg(bv + lane) + BN_EPS_F) * tl2;
    float eps2 = GEN_EPS_F * tl2;

    int p0 = d_rowptr[node], p1 = d_rowptr[node + 1];
    int idx = node * CC + lane;
    if (p0 >= p1) { d_h2[idx] = d_h[idx]; return; }

    float mxl = -3.402823466e38f, den = 0.0f, num = 0.0f;
    const short* eqp = d_eq + (size_t)p0 * CC + lane;

    #pragma unroll 4
    for (int p = p0; p < p1; ++p) {
        int   src = __ldcs(d_srcp + p);
        short kv  = __ldcs(eqp);
        eqp += CC;
        float hbv = __ldg(d_hb + src * CC + lane);      // pre-scaled by tl2
        float sl  = fmaxf(fmaf((float)kv, A2, hbv), eps2);
        float nm  = fmaxf(mxl, sl);
        float ea  = ex2f(sl - nm);
        float eb  = ex2f(mxl - nm);
        den = fmaf(den, eb, ea);
        num = fmaf(num, eb, ea * sl);
        mxl = nm;
    }
    float agg = num / (fmaxf(den, 1e-16f) * tl2);       // undo tl2 scaling
    d_h2[idx] = d_h[idx] + agg;
}

// ---------------- per-layer quantized MLP + residual (+ scaled hb emit) ----------
__global__ void __launch_bounds__(128) k_mlp(int l,
        const float* __restrict__ W1, const float* __restrict__ b1,
        const float* __restrict__ g1, const float* __restrict__ bb1,
        const float* __restrict__ m1, const float* __restrict__ v1,
        const float* __restrict__ W2, const float* __restrict__ b2,
        const float* __restrict__ eg, const float* __restrict__ eb,
        const float* __restrict__ em, const float* __restrict__ ev,
        const float* __restrict__ t) {
    __shared__ float w1s[CC * 2 * CC];
    __shared__ float w2s[2 * CC * CC];
    __shared__ float b1s[2 * CC], a1s[2 * CC], d1s[2 * CC], b2s[CC], Es[CC];
    int tid = threadIdx.x;
    const float* W1l = W1 + l * CC * 2 * CC;
    const float* W2l = W2 + l * 2 * CC * CC;
    for (int i = tid; i < CC * 2 * CC; i += 128) {
        w1s[i] = qf(W1l[i]);
        w2s[i] = qf(W2l[i]);
    }
    if (tid < 2 * CC) {
        b1s[tid] = qf(b1[l * 2 * CC + tid]);
        float rsv = rsqrtf(v1[l * 2 * CC + tid] + BN_EPS_F);
        float a = g1[l * 2 * CC + tid] * rsv;
        a1s[tid] = a;
        d1s[tid] = bb1[l * 2 * CC + tid] - m1[l * 2 * CC + tid] * a;
    }
    if (tid < CC) {
        b2s[tid] = qf(b2[l * CC + tid]);
        float ga = eg[tid] * rsqrtf(ev[tid] + BN_EPS_F);
        Es[tid] = eb[tid] - em[tid] * ga + GEN_EPS_F;
    }
    __syncthreads();

    int node = blockIdx.x * 128 + tid;
    if (node >= NN) return;

    float xq[CC];
    const float4* hp = (const float4*)(d_h2 + node * CC);
    #pragma unroll
    for (int i = 0; i < 8; i++) {
        float4 t4 = hp[i];
        xq[4 * i + 0] = qf(t4.x); xq[4 * i + 1] = qf(t4.y);
        xq[4 * i + 2] = qf(t4.z); xq[4 * i + 3] = qf(t4.w);
    }
    float acc2[CC];
    #pragma unroll
    for (int c = 0; c < CC; c++) acc2[c] = b2s[c];

    for (int j = 0; j < 2 * CC; j++) {
        float a = b1s[j];
        #pragma unroll
        for (int k = 0; k < CC; k++) a = fmaf(xq[k], w1s[k * 2 * CC + j], a);
        float z1 = qf(a);
        float zr = qf(fmaxf(fmaf(a1s[j], z1, d1s[j]), 0.0f));
        #pragma unroll
        for (int c = 0; c < CC; c++) acc2[c] = fmaf(zr, w2s[j * CC + c], acc2[c]);
    }
    bool emit_hb = (l < LL - 1);
    float tl2n = emit_hb ? __ldg(t + l + 1) * LOG2E_F : 0.0f;
    const float4* ip = (const float4*)(d_h + node * CC);
    float4* op = (float4*)(d_h + node * CC);
    float4* bp = (float4*)(d_hb + node * CC);
    #pragma unroll
    for (int c = 0; c < CC; c += 4) {
        float4 id4 = ip[c >> 2];
        float4 o;
        o.x = qf(acc2[c + 0]) + id4.x;
        o.y = qf(acc2[c + 1]) + id4.y;
        o.z = qf(acc2[c + 2]) + id4.z;
        o.w = qf(acc2[c + 3]) + id4.w;
        op[c >> 2] = o;
        if (emit_hb) {
            float4 hbv;
            hbv.x = (o.x + Es[c + 0]) * tl2n;
            hbv.y = (o.y + Es[c + 1]) * tl2n;
            hbv.z = (o.z + Es[c + 2]) * tl2n;
            hbv.w = (o.w + Es[c + 3]) * tl2n;
            bp[c >> 2] = hbv;
        }
    }
}

// ---------------- global mean pool ----------------------------------------------
__global__ void k_pool(const int* __restrict__ batch) {
    int lane = threadIdx.x & 31;
    int w = (blockIdx.x * blockDim.x + threadIdx.x) >> 5;
    const int CHUNK = 128;
    int i0 = w * CHUNK;
    if (i0 >= NN) return;
    int i1 = min(i0 + CHUNK, NN);
    int cur = batch[i0];
    float acc = 0.0f;
    for (int i = i0; i < i1; i++) {
        int g = batch[i];
        float val = d_h[i * CC + lane];
        if (g != cur) {
            atomicAdd(&d_pool[cur * CC + lane], acc);
            acc = 0.0f;
            cur = g;
        }
        acc += val;
    }
    atomicAdd(&d_pool[cur * CC + lane], acc);
}

__global__ void k_cnt(const int* __restrict__ batch) {
    int g = blockIdx.x * blockDim.x + threadIdx.x;
    if (g >= GG) return;
    int lo0 = 0, hi0 = NN;
    while (lo0 < hi0) { int mid = (lo0 + hi0) >> 1; if (batch[mid] < g) lo0 = mid + 1; else hi0 = mid; }
    int lo1 = lo0, hi1 = NN;
    while (lo1 < hi1) { int mid = (lo1 + hi1) >> 1; if (batch[mid] < g + 1) lo1 = mid + 1; else hi1 = mid; }
    d_cntf[g] = (float)(lo1 - lo0);
}

__global__ void k_final(const float* __restrict__ Wo, const float* __restrict__ bo,
                        float* __restrict__ out) {
    __shared__ float wq[CC];
    int tid = threadIdx.x;
    if (tid < CC) wq[tid] = qf(Wo[tid]);
    __syncthreads();
    int g = blockIdx.x * blockDim.x + tid;
    if (g >= GG) return;
    float cnt = fmaxf(d_cntf[g], 1.0f);
    float acc = qf(bo[0]);
    #pragma unroll
    for (int c = 0; c < CC; c++) {
        float pm = d_pool[g * CC + c] / cnt;
        acc = fmaf(qf(pm), wq[c], acc);
    }
    float o = qf(acc);
    float s = 1.0f / (1.0f + expf(-o));
    out[g] = qf(s);
}

// ---------------- launch ---------------------------------------------------------
extern "C" void kernel_launch(void* const* d_in, const int* in_sizes, int n_in,
                              void* d_out, int out_size) {
    const float* x    = (const float*)d_in[0];
    const float* ea   = (const float*)d_in[1];
    const float* Wn   = (const float*)d_in[2];
    const float* bn_  = (const float*)d_in[3];
    const float* We   = (const float*)d_in[4];
    const float* be   = (const float*)d_in[5];
    const float* bnng = (const float*)d_in[6];
    const float* bnnb = (const float*)d_in[7];
    const float* bnnm = (const float*)d_in[8];
    const float* bnnv = (const float*)d_in[9];
    const float* bneg = (const float*)d_in[10];
    const float* bneb = (const float*)d_in[11];
    const float* bnem = (const float*)d_in[12];
    const float* bnev = (const float*)d_in[13];
    const float* t    = (const float*)d_in[14];
    const float* W1   = (const float*)d_in[15];
    const float* b1   = (const float*)d_in[16];
    const float* g1   = (const float*)d_in[17];
    const float* bb1  = (const float*)d_in[18];
    const float* m1   = (const float*)d_in[19];
    const float* v1   = (const float*)d_in[20];
    const float* W2   = (const float*)d_in[21];
    const float* b2   = (const float*)d_in[22];
    const float* Wo   = (const float*)d_in[23];
    const float* bo   = (const float*)d_in[24];
    const int*   ei   = (const int*)d_in[25];
    const int*   batch= (const int*)d_in[26];
    float* out = (float*)d_out;

    k_pre<<<(EE + 255) / 256, 256>>>(x, Wn, bn_, bnng, bnnb, bnnm, bnnv,
                                     bneg, bneb, bnem, bnev, t, ei);
    k_scan<<<SCAN_NB, 1024>>>();
    k_epack<<<(EE + 255) / 256, 256>>>(ea, ei);
    k_eexpand<<<(EE + 255) / 256, 256>>>(We, be);

    for (int l = 0; l < LL; l++) {
        k_agg<<<(NN + 7) / 8, 256>>>(t, l, bneg, bnev);
        k_mlp<<<(NN + 127) / 128, 128>>>(l, W1, b1, g1, bb1, m1, v1, W2, b2,
                                         bneg, bneb, bnem, bnev, t);
    }

    k_pool<<<98, 256>>>(batch);
    k_cnt<<<(GG + 255) / 256, 256>>>(batch);
    k_final<<<(GG + 255) / 256, 256>>>(Wo, bo, out);
}